// round 9
// baseline (speedup 1.0000x reference)
#include <cuda_runtime.h>
#include <cuda_bf16.h>
#include <cstdint>
#include <math.h>

// ---------------- scratch (device globals; no allocations allowed) ----------
#define NMAX 50000
__device__ float  g_xh[(size_t)NMAX * 128];  // [N, H*D] = [N,128]
__device__ float  g_s [NMAX * 4];            // (si0, si1, sj0, sj1) per node
__device__ double g_wd[NMAX];                // packed: deg*2^20 + sum(alpha0), excl self

// ---------------- PTX helpers (base sm_103 target) --------------------------
__device__ __forceinline__ uint32_t smem_u32(const void* p) {
    uint32_t a;
    asm("{ .reg .u64 t; cvta.to.shared.u64 t, %1; cvt.u32.u64 %0, t; }"
        : "=r"(a) : "l"(p));
    return a;
}
__device__ __forceinline__ void ldsm_x4(uint32_t& r0, uint32_t& r1,
                                        uint32_t& r2, uint32_t& r3, uint32_t addr) {
    asm volatile("ldmatrix.sync.aligned.m8n8.x4.shared.b16 {%0,%1,%2,%3}, [%4];"
                 : "=r"(r0), "=r"(r1), "=r"(r2), "=r"(r3) : "r"(addr));
}
__device__ __forceinline__ void ldsm_x4t(uint32_t& r0, uint32_t& r1,
                                         uint32_t& r2, uint32_t& r3, uint32_t addr) {
    asm volatile("ldmatrix.sync.aligned.m8n8.x4.trans.shared.b16 {%0,%1,%2,%3}, [%4];"
                 : "=r"(r0), "=r"(r1), "=r"(r2), "=r"(r3) : "r"(addr));
}
__device__ __forceinline__ void mma16816(float* c, const uint32_t* a, const uint32_t* b) {
    asm volatile(
        "mma.sync.aligned.m16n8k16.row.col.f32.bf16.bf16.f32 "
        "{%0,%1,%2,%3}, {%4,%5,%6,%7}, {%8,%9}, {%0,%1,%2,%3};"
        : "+f"(c[0]), "+f"(c[1]), "+f"(c[2]), "+f"(c[3])
        : "r"(a[0]), "r"(a[1]), "r"(a[2]), "r"(a[3]), "r"(b[0]), "r"(b[1]));
}

__device__ __forceinline__ void split4(float4 v, uint2& hi, uint2& lo) {
    __nv_bfloat16 hx = __float2bfloat16(v.x), hy = __float2bfloat16(v.y);
    __nv_bfloat16 hz = __float2bfloat16(v.z), hw = __float2bfloat16(v.w);
    __nv_bfloat16 lx = __float2bfloat16(v.x - __bfloat162float(hx));
    __nv_bfloat16 ly = __float2bfloat16(v.y - __bfloat162float(hy));
    __nv_bfloat16 lz = __float2bfloat16(v.z - __bfloat162float(hz));
    __nv_bfloat16 lw = __float2bfloat16(v.w - __bfloat162float(hw));
    hi.x = (uint32_t)__bfloat16_as_ushort(hx) | ((uint32_t)__bfloat16_as_ushort(hy) << 16);
    hi.y = (uint32_t)__bfloat16_as_ushort(hz) | ((uint32_t)__bfloat16_as_ushort(hw) << 16);
    lo.x = (uint32_t)__bfloat16_as_ushort(lx) | ((uint32_t)__bfloat16_as_ushort(ly) << 16);
    lo.y = (uint32_t)__bfloat16_as_ushort(lz) | ((uint32_t)__bfloat16_as_ushort(lw) << 16);
}

// ---------------- SMEM layout (bytes) ----------------------------------------
// A: 64 m-rows x KP(136) bf16 -> 272B rows (16 mod 128: conflict-free ldsm)
// B: 128 k-rows x KPB(72) bf16 -> 144B rows (16 mod 128: conflict-free ldsm.t)
#define KP  136
#define KPB 72
#define O_ATT   0                       // 512 floats = 2048B
#define O_PSI   2048                    // [4 colgroups][64 rows] = 1024B
#define O_PSJ   3072                    // 1024B
#define O_AH    4096                    // 17408B
#define O_AL    (O_AH + 17408)
#define O_BH    (O_AL + 17408)          // 18432B
#define O_BL    (O_BH + 18432)
#define SMEM_TOTAL (O_BL + 18432)       // 75776 -> 3 CTAs/SM

// ---------------- Kernel 1: persistent fused GEMM + scores -------------------
// CTA covers 64 rows x 64 cols (one head). ch = blockIdx.x & 1 selects head.
__global__ __launch_bounds__(256, 3)
void fused_gemm_kernel(const float* __restrict__ x,
                       const float* __restrict__ W,
                       const float* __restrict__ emb,
                       const float* __restrict__ ai,  const float* __restrict__ aj,
                       const float* __restrict__ aei, const float* __restrict__ aej,
                       int N, int ntiles)
{
    extern __shared__ char sm[];
    const uint32_t smb = smem_u32(sm);
    const int tid = threadIdx.x;
    const int wid = tid >> 5;
    const int lid = tid & 31;
    const int ch  = blockIdx.x & 1;      // head / column half

    // ---- stage B ONCE: W[:, ch*64 .. ch*64+63], bf16 hi/lo split --------------
#pragma unroll
    for (int i = 0; i < 8; i++) {
        int idx = tid + i * 256;            // over 2048 float4s
        int k = idx >> 4, n = (idx & 15) * 4;
        float4 v = *(const float4*)(W + (size_t)k * 128 + ch * 64 + n);
        uint2 hi, lo;
        split4(v, hi, lo);
        uint32_t off = (uint32_t)(k * KPB + n) * 2;
        *(uint2*)(sm + O_BH + off) = hi;
        *(uint2*)(sm + O_BL + off) = lo;
    }
    // ---- stage attention vectors ---------------------------------------------
    {
        float* satt = (float*)(sm + O_ATT);
#pragma unroll
        for (int i = 0; i < 2; i++) {
            int t = tid + i * 256;
            float v;
            if      (t < 128) v = ai [t];
            else if (t < 256) v = aj [t - 128];
            else if (t < 384) v = aei[t - 256];
            else              v = aej[t - 384];
            satt[t] = v;
        }
    }

    // warp tile: 32 rows x 16 cols. wr = wid&1 (row grp), wc = wid>>1 (col grp 0..3)
    const int mrow = (wid & 1) * 32;
    const int nc16 = (wid >> 1) * 16;
    const int g    = lid >> 2, tig = lid & 3;

    const int l15 = lid & 15;
    const int lh8 = (lid >> 4) * 8;
    const uint32_t aoff = (uint32_t)((mrow + l15) * KP + lh8) * 2;
    const int bkr = ((lid >> 3) & 1) * 8 + (lid & 7);
    const int bnc = (lid >> 4) * 8;
    const uint32_t boff = (uint32_t)(bkr * KPB + nc16 + bnc) * 2;

    const float* satt = (const float*)(sm + O_ATT);
    const float* attiq = satt + ch * 64 + nc16;            // 16 cols of head ch
    const float* attjq = satt + 128 + ch * 64 + nc16;
    const float* aeiq  = satt + 256 + ch * 64 + tig * 16;
    const float* aejq  = satt + 384 + ch * 64 + tig * 16;
    float* psiA = (float*)(sm + O_PSI);
    float* psjA = (float*)(sm + O_PSJ);

    for (int tile = blockIdx.x >> 1; tile < ntiles; tile += gridDim.x >> 1) {
        const int row0 = tile * 64;

        // ---- stage A tile (bf16 hi/lo split) ----------------------------------
#pragma unroll
        for (int i = 0; i < 8; i++) {
            int idx = tid + i * 256;
            int r = idx >> 5, c = (idx & 31) * 4;
            float4 v = make_float4(0.f, 0.f, 0.f, 0.f);
            if (row0 + r < N) v = *(const float4*)(x + (size_t)(row0 + r) * 128 + c);
            uint2 hi, lo;
            split4(v, hi, lo);
            uint32_t off = (uint32_t)(r * KP + c) * 2;
            *(uint2*)(sm + O_AH + off) = hi;
            *(uint2*)(sm + O_AL + off) = lo;
        }
        __syncthreads();

        // ---- MMA ----------------------------------------------------------------
        float acc[2][2][4];
#pragma unroll
        for (int t = 0; t < 2; t++)
#pragma unroll
            for (int n = 0; n < 2; n++)
#pragma unroll
                for (int k = 0; k < 4; k++) acc[t][n][k] = 0.f;

#pragma unroll
        for (int ks = 0; ks < 8; ks++) {
            const uint32_t akb = (uint32_t)ks * 32;
            const uint32_t bkb = (uint32_t)ks * (16 * KPB * 2);
            uint32_t ah[2][4], al[2][4], b[2][2];

#pragma unroll
            for (int t = 0; t < 2; t++)
                ldsm_x4(ah[t][0], ah[t][1], ah[t][2], ah[t][3],
                        smb + O_AH + aoff + (uint32_t)t * (16 * KP * 2) + akb);
            ldsm_x4t(b[0][0], b[0][1], b[1][0], b[1][1],
                     smb + O_BH + boff + bkb);
#pragma unroll
            for (int t = 0; t < 2; t++)
#pragma unroll
                for (int n = 0; n < 2; n++) mma16816(acc[t][n], ah[t], b[n]);

#pragma unroll
            for (int t = 0; t < 2; t++)
                ldsm_x4(al[t][0], al[t][1], al[t][2], al[t][3],
                        smb + O_AL + aoff + (uint32_t)t * (16 * KP * 2) + akb);
#pragma unroll
            for (int t = 0; t < 2; t++)
#pragma unroll
                for (int n = 0; n < 2; n++) mma16816(acc[t][n], al[t], b[n]);

            ldsm_x4t(b[0][0], b[0][1], b[1][0], b[1][1],
                     smb + O_BL + boff + bkb);
#pragma unroll
            for (int t = 0; t < 2; t++)
#pragma unroll
                for (int n = 0; n < 2; n++) mma16816(acc[t][n], ah[t], b[n]);
        }

        // ---- direct coalesced-sector writeout of xh fragments -------------------
#pragma unroll
        for (int t = 0; t < 2; t++)
#pragma unroll
            for (int n = 0; n < 2; n++) {
                int r = row0 + mrow + t * 16 + g;
                int c = ch * 64 + nc16 + n * 8 + tig * 2;
                if (r < N)
                    *(float2*)(g_xh + (size_t)r * 128 + c) = make_float2(acc[t][n][0], acc[t][n][1]);
                if (r + 8 < N)
                    *(float2*)(g_xh + (size_t)(r + 8) * 128 + c) = make_float2(acc[t][n][2], acc[t][n][3]);
            }

        // ---- partial scores for this warp's 16 columns (head ch) ----------------
        float psi[4], psj[4];
#pragma unroll
        for (int t = 0; t < 2; t++)
#pragma unroll
            for (int h = 0; h < 2; h++) {
                float si = 0.f, sj = 0.f;
#pragma unroll
                for (int n = 0; n < 2; n++) {
                    int c = n * 8 + tig * 2;
                    float v0 = acc[t][n][h * 2 + 0];
                    float v1 = acc[t][n][h * 2 + 1];
                    si += v0 * attiq[c] + v1 * attiq[c + 1];
                    sj += v0 * attjq[c] + v1 * attjq[c + 1];
                }
                if (nc16 == 0) {   // add embedding term once per (row, head)
                    int grow = row0 + mrow + t * 16 + h * 8 + g;
                    if (grow < N) {
                        const float4* er = (const float4*)(emb + (size_t)grow * 64 + tig * 16);
#pragma unroll
                        for (int e4 = 0; e4 < 4; e4++) {
                            float4 e = er[e4];
                            si += e.x * aeiq[e4 * 4 + 0] + e.y * aeiq[e4 * 4 + 1]
                                + e.z * aeiq[e4 * 4 + 2] + e.w * aeiq[e4 * 4 + 3];
                            sj += e.x * aejq[e4 * 4 + 0] + e.y * aejq[e4 * 4 + 1]
                                + e.z * aejq[e4 * 4 + 2] + e.w * aejq[e4 * 4 + 3];
                        }
                    }
                }
                psi[t * 2 + h] = si;
                psj[t * 2 + h] = sj;
            }
#pragma unroll
        for (int r = 0; r < 4; r++) {
            psi[r] += __shfl_xor_sync(0xffffffffu, psi[r], 1);
            psi[r] += __shfl_xor_sync(0xffffffffu, psi[r], 2);
            psj[r] += __shfl_xor_sync(0xffffffffu, psj[r], 1);
            psj[r] += __shfl_xor_sync(0xffffffffu, psj[r], 2);
        }
        if (tig == 0) {
            int wc = wid >> 1;
#pragma unroll
            for (int t = 0; t < 2; t++)
#pragma unroll
                for (int h = 0; h < 2; h++) {
                    int lrow = mrow + t * 16 + h * 8 + g;
                    psiA[wc * 64 + lrow] = psi[t * 2 + h];
                    psjA[wc * 64 + lrow] = psj[t * 2 + h];
                }
        }
        __syncthreads();

        // ---- combine partials, emit this head's scores ---------------------------
        if (tid < 64) {
            int grow = row0 + tid;
            if (grow < N) {
                float si = psiA[tid] + psiA[64 + tid] + psiA[128 + tid] + psiA[192 + tid];
                float sj = psjA[tid] + psjA[64 + tid] + psjA[128 + tid] + psjA[192 + tid];
                g_s[4 * grow + ch]     = si;
                g_s[4 * grow + 2 + ch] = sj;
                if (ch == 0) g_wd[grow] = 0.0;
            }
        }
        __syncthreads();   // protect A tiles + psi arrays before next iteration
    }
}

// ---------------- Kernel 2: per-edge attention, 4 edges/thread ---------------
__device__ __forceinline__ float edge_alpha0(float2 si, float2 sj) {
    float a0 = si.x + sj.x;  a0 = fmaxf(a0, 0.2f * a0);
    float a1 = si.y + sj.y;  a1 = fmaxf(a1, 0.2f * a1);
    return __fdividef(1.0f, 1.0f + __expf(a1 - a0));   // = e0/(e0+e1)
}

__global__ void edge_kernel(const int* __restrict__ src, const int* __restrict__ dst,
                            int Eq)
{
    int i = blockIdx.x * blockDim.x + threadIdx.x;
    if (i >= Eq) return;
    int4 s4 = ((const int4*)src)[i];
    int4 d4 = ((const int4*)dst)[i];

    float2 si_a = *(const float2*)(g_s + 4 * s4.x);
    float2 sj_a = *(const float2*)(g_s + 4 * d4.x + 2);
    float2 si_b = *(const float2*)(g_s + 4 * s4.y);
    float2 sj_b = *(const float2*)(g_s + 4 * d4.y + 2);
    float2 si_c = *(const float2*)(g_s + 4 * s4.z);
    float2 sj_c = *(const float2*)(g_s + 4 * d4.z + 2);
    float2 si_d = *(const float2*)(g_s + 4 * s4.w);
    float2 sj_d = *(const float2*)(g_s + 4 * d4.w + 2);

    float aa = edge_alpha0(si_a, sj_a);
    float ab = edge_alpha0(si_b, sj_b);
    float ac = edge_alpha0(si_c, sj_c);
    float ad = edge_alpha0(si_d, sj_d);

    atomicAdd(g_wd + d4.x, (double)aa + 1048576.0);
    atomicAdd(g_wd + d4.y, (double)ab + 1048576.0);
    atomicAdd(g_wd + d4.z, (double)ac + 1048576.0);
    atomicAdd(g_wd + d4.w, (double)ad + 1048576.0);
}

// ---------------- Kernel 3: out = 0.5*(xh0*w0 + xh1*w1), self-loop inline ----
// (round-7 shape: 8 cols/thread, measured fastest)
__global__ void out_kernel(float* __restrict__ out, int N)
{
    int i = blockIdx.x * blockDim.x + threadIdx.x;   // over N*8 items
    if (i >= N * 8) return;
    int n  = i >> 3;
    int d8 = (i & 7) << 3;

    float4 ss = *(const float4*)(g_s + 4 * n);
    float aself = edge_alpha0(make_float2(ss.x, ss.y), make_float2(ss.z, ss.w));

    double v   = g_wd[n];
    double deg = floor(v * 9.5367431640625e-07);       // v / 2^20
    float  w0  = (float)(v - deg * 1048576.0) + aself;
    float  w1  = ((float)deg + 1.0f) - w0;

    const float* xr = g_xh + (size_t)n * 128;
    float4 av0 = *(const float4*)(xr + d8);
    float4 av1 = *(const float4*)(xr + d8 + 4);
    float4 bv0 = *(const float4*)(xr + 64 + d8);
    float4 bv1 = *(const float4*)(xr + 64 + d8 + 4);

    float4 o0, o1;
    o0.x = 0.5f * (av0.x * w0 + bv0.x * w1);
    o0.y = 0.5f * (av0.y * w0 + bv0.y * w1);
    o0.z = 0.5f * (av0.z * w0 + bv0.z * w1);
    o0.w = 0.5f * (av0.w * w0 + bv0.w * w1);
    o1.x = 0.5f * (av1.x * w0 + bv1.x * w1);
    o1.y = 0.5f * (av1.y * w0 + bv1.y * w1);
    o1.z = 0.5f * (av1.z * w0 + bv1.z * w1);
    o1.w = 0.5f * (av1.w * w0 + bv1.w * w1);
    *(float4*)(out + (size_t)n * 64 + d8)     = o0;
    *(float4*)(out + (size_t)n * 64 + d8 + 4) = o1;
}

// ---------------- launcher ---------------------------------------------------
extern "C" void kernel_launch(void* const* d_in, const int* in_sizes, int n_in,
                              void* d_out, int out_size)
{
    const float* x    = (const float*)d_in[0];
    const float* emb  = (const float*)d_in[1];
    const float* W    = (const float*)d_in[2];
    const float* ai   = (const float*)d_in[3];
    const float* aj   = (const float*)d_in[4];
    const float* aei  = (const float*)d_in[5];
    const float* aej  = (const float*)d_in[6];
    const int*   esrc = (const int*)d_in[7];
    const int*   edst = (const int*)d_in[8];
    float* out = (float*)d_out;

    const int N = in_sizes[0] / 128;   // 50000
    const int E = in_sizes[7];         // 1600000 (divisible by 4)
    const int ntiles = (N + 63) / 64;  // 782
    int grid = 444;                    // 3 CTAs/SM x 148 SMs
    if (grid > 2 * ntiles) grid = 2 * ntiles;
    grid &= ~1;                        // keep even (ch pairing)

    cudaFuncSetAttribute(fused_gemm_kernel,
                         cudaFuncAttributeMaxDynamicSharedMemorySize, SMEM_TOTAL);

    fused_gemm_kernel<<<grid, 256, SMEM_TOTAL>>>(x, W, emb, ai, aj, aei, aej, N, ntiles);
    const int Eq = E / 4;
    edge_kernel<<<(Eq + 255) / 256, 256>>>(esrc, edst, Eq);
    out_kernel<<<(N * 8 + 255) / 256, 256>>>(out, N);
}

// round 10
// speedup vs baseline: 1.0631x; 1.0631x over previous
#include <cuda_runtime.h>
#include <cuda_bf16.h>
#include <cstdint>
#include <math.h>

// ---------------- scratch (device globals; no allocations allowed) ----------
#define NMAX 50000
__device__ float  g_xh[(size_t)NMAX * 128];  // [N, H*D] = [N,128]
__device__ float  g_s [NMAX * 4];            // (si0, si1, sj0, sj1) per node
__device__ double g_wd[NMAX];                // packed: deg*2^20 + sum(alpha0), excl self
__device__ __nv_bfloat16 g_wh[128 * 128];    // W hi, natural [k][n]
__device__ __nv_bfloat16 g_wl[128 * 128];    // W lo

// ---------------- PTX helpers (base sm_103 target) --------------------------
__device__ __forceinline__ uint32_t smem_u32(const void* p) {
    uint32_t a;
    asm("{ .reg .u64 t; cvta.to.shared.u64 t, %1; cvt.u32.u64 %0, t; }"
        : "=r"(a) : "l"(p));
    return a;
}
__device__ __forceinline__ void ldsm_x4(uint32_t& r0, uint32_t& r1,
                                        uint32_t& r2, uint32_t& r3, uint32_t addr) {
    asm volatile("ldmatrix.sync.aligned.m8n8.x4.shared.b16 {%0,%1,%2,%3}, [%4];"
                 : "=r"(r0), "=r"(r1), "=r"(r2), "=r"(r3) : "r"(addr));
}
__device__ __forceinline__ void ldsm_x4t(uint32_t& r0, uint32_t& r1,
                                         uint32_t& r2, uint32_t& r3, uint32_t addr) {
    asm volatile("ldmatrix.sync.aligned.m8n8.x4.trans.shared.b16 {%0,%1,%2,%3}, [%4];"
                 : "=r"(r0), "=r"(r1), "=r"(r2), "=r"(r3) : "r"(addr));
}
__device__ __forceinline__ void mma16816(float* c, const uint32_t* a, const uint32_t* b) {
    asm volatile(
        "mma.sync.aligned.m16n8k16.row.col.f32.bf16.bf16.f32 "
        "{%0,%1,%2,%3}, {%4,%5,%6,%7}, {%8,%9}, {%0,%1,%2,%3};"
        : "+f"(c[0]), "+f"(c[1]), "+f"(c[2]), "+f"(c[3])
        : "r"(a[0]), "r"(a[1]), "r"(a[2]), "r"(a[3]), "r"(b[0]), "r"(b[1]));
}

__device__ __forceinline__ void split4(float4 v, uint2& hi, uint2& lo) {
    __nv_bfloat16 hx = __float2bfloat16(v.x), hy = __float2bfloat16(v.y);
    __nv_bfloat16 hz = __float2bfloat16(v.z), hw = __float2bfloat16(v.w);
    __nv_bfloat16 lx = __float2bfloat16(v.x - __bfloat162float(hx));
    __nv_bfloat16 ly = __float2bfloat16(v.y - __bfloat162float(hy));
    __nv_bfloat16 lz = __float2bfloat16(v.z - __bfloat162float(hz));
    __nv_bfloat16 lw = __float2bfloat16(v.w - __bfloat162float(hw));
    hi.x = (uint32_t)__bfloat16_as_ushort(hx) | ((uint32_t)__bfloat16_as_ushort(hy) << 16);
    hi.y = (uint32_t)__bfloat16_as_ushort(hz) | ((uint32_t)__bfloat16_as_ushort(hw) << 16);
    lo.x = (uint32_t)__bfloat16_as_ushort(lx) | ((uint32_t)__bfloat16_as_ushort(ly) << 16);
    lo.y = (uint32_t)__bfloat16_as_ushort(lz) | ((uint32_t)__bfloat16_as_ushort(lw) << 16);
}

// ---------------- SMEM layout (bytes) ----------------------------------------
#define KP 136
#define O_ATT   0                       // 512 floats = 2048B
#define O_PSI   2048                    // 1024B
#define O_PSJ   3072                    // 1024B
#define O_AH    4096                    // A hi  [64 m][KP k]  = 17408B
#define O_AL    (O_AH + 17408)
#define O_BH    (O_AL + 17408)          // B hi  [128 k][KP n] = 34816B
#define O_BL    (O_BH + 34816)
#define SMEM_TOTAL (O_BL + 34816)       // 108544 -> 2 CTAs/SM

// ---------------- Kernel 0: precompute W bf16 hi/lo split --------------------
__global__ void wsplit_kernel(const float* __restrict__ W)
{
    int i = blockIdx.x * blockDim.x + threadIdx.x;   // over 4096 float4s
    if (i >= 128 * 128 / 4) return;
    float4 v = ((const float4*)W)[i];
    uint2 hi, lo;
    split4(v, hi, lo);
    ((uint2*)g_wh)[i] = hi;
    ((uint2*)g_wl)[i] = lo;
}

// ---------------- Kernel 1: persistent fused GEMM + scores -------------------
// 64-row x 128-col tile, 256 threads; A tile prefetched into regs across tiles
__global__ __launch_bounds__(256, 2)
void fused_gemm_kernel(const float* __restrict__ x,
                       const float* __restrict__ emb,
                       const float* __restrict__ ai,  const float* __restrict__ aj,
                       const float* __restrict__ aei, const float* __restrict__ aej,
                       int N, int ntiles)
{
    extern __shared__ char sm[];
    const uint32_t smb = smem_u32(sm);
    const int tid = threadIdx.x;
    const int wid = tid >> 5;
    const int lid = tid & 31;

    // ---- stage B ONCE: pure copy of precomputed split (uint4 = 8 bf16) -------
#pragma unroll
    for (int i = 0; i < 8; i++) {
        int idx = tid + i * 256;            // over 2048 uint4s
        int k = idx >> 4, n = (idx & 15) * 8;
        uint32_t off = (uint32_t)(k * KP + n) * 2;
        *(uint4*)(sm + O_BH + off) = ((const uint4*)g_wh)[idx];
        *(uint4*)(sm + O_BL + off) = ((const uint4*)g_wl)[idx];
    }
    // ---- stage attention vectors ---------------------------------------------
    {
        float* satt = (float*)(sm + O_ATT);
#pragma unroll
        for (int i = 0; i < 2; i++) {
            int t = tid + i * 256;
            float v;
            if      (t < 128) v = ai [t];
            else if (t < 256) v = aj [t - 128];
            else if (t < 384) v = aei[t - 256];
            else              v = aej[t - 384];
            satt[t] = v;
        }
    }

    // warp tile coords (constant across tiles)
    const int mrow = (wid & 1) * 32;
    const int ncol = (wid >> 1) * 32;
    const int q    = ncol >> 6;
    const int cg   = (ncol >> 5) & 1;
    const int g    = lid >> 2, tig = lid & 3;

    const int l15 = lid & 15;
    const int lh8 = (lid >> 4) * 8;
    const uint32_t aoff = (uint32_t)((mrow + l15) * KP + lh8) * 2;
    const int bkr = ((lid >> 3) & 1) * 8 + (lid & 7);
    const int bnc = (lid >> 4) * 8;
    const uint32_t boff = (uint32_t)(bkr * KP + ncol + bnc) * 2;

    const float* satt = (const float*)(sm + O_ATT);
    const float* attiq = satt + q * 64 + cg * 32;
    const float* attjq = satt + 128 + q * 64 + cg * 32;
    const float* aeiq  = satt + 256 + q * 64 + tig * 16;
    const float* aejq  = satt + 384 + q * 64 + tig * 16;
    float* psiA = (float*)(sm + O_PSI);
    float* psjA = (float*)(sm + O_PSJ);

    // ---- prologue: prefetch first tile's A rows into registers ---------------
    float4 v[8];
    {
        int row0 = blockIdx.x * 64;
#pragma unroll
        for (int i = 0; i < 8; i++) {
            int idx = tid + i * 256;
            int r = idx >> 5, c = (idx & 31) * 4;
            v[i] = (row0 + r < N) ? *(const float4*)(x + (size_t)(row0 + r) * 128 + c)
                                  : make_float4(0.f, 0.f, 0.f, 0.f);
        }
    }

    for (int tile = blockIdx.x; tile < ntiles; tile += gridDim.x) {
        const int row0 = tile * 64;

        // ---- split prefetched A into SMEM (bf16 hi/lo) --------------------------
#pragma unroll
        for (int i = 0; i < 8; i++) {
            int idx = tid + i * 256;
            int r = idx >> 5, c = (idx & 31) * 4;
            uint2 hi, lo;
            split4(v[i], hi, lo);
            uint32_t off = (uint32_t)(r * KP + c) * 2;
            *(uint2*)(sm + O_AH + off) = hi;
            *(uint2*)(sm + O_AL + off) = lo;
        }
        __syncthreads();

        // ---- prefetch NEXT tile's A (latency hidden behind MMA loop) ------------
        {
            int nt = tile + gridDim.x;
            if (nt < ntiles) {
                int nrow0 = nt * 64;
#pragma unroll
                for (int i = 0; i < 8; i++) {
                    int idx = tid + i * 256;
                    int r = idx >> 5, c = (idx & 31) * 4;
                    v[i] = (nrow0 + r < N)
                         ? *(const float4*)(x + (size_t)(nrow0 + r) * 128 + c)
                         : make_float4(0.f, 0.f, 0.f, 0.f);
                }
            }
        }

        // ---- MMA ----------------------------------------------------------------
        float acc[2][4][4];
#pragma unroll
        for (int t = 0; t < 2; t++)
#pragma unroll
            for (int n = 0; n < 4; n++)
#pragma unroll
                for (int k = 0; k < 4; k++) acc[t][n][k] = 0.f;

#pragma unroll
        for (int ks = 0; ks < 8; ks++) {
            const uint32_t akb = (uint32_t)ks * 32;
            const uint32_t bkb = (uint32_t)ks * (16 * KP * 2);
            uint32_t ah[2][4], al[2][4], b[4][2];

#pragma unroll
            for (int t = 0; t < 2; t++)
                ldsm_x4(ah[t][0], ah[t][1], ah[t][2], ah[t][3],
                        smb + O_AH + aoff + (uint32_t)t * (16 * KP * 2) + akb);
#pragma unroll
            for (int p = 0; p < 2; p++)
                ldsm_x4t(b[2 * p][0], b[2 * p][1], b[2 * p + 1][0], b[2 * p + 1][1],
                         smb + O_BH + boff + bkb + (uint32_t)p * 32);
#pragma unroll
            for (int t = 0; t < 2; t++)
#pragma unroll
                for (int n = 0; n < 4; n++) mma16816(acc[t][n], ah[t], b[n]);

#pragma unroll
            for (int t = 0; t < 2; t++)
                ldsm_x4(al[t][0], al[t][1], al[t][2], al[t][3],
                        smb + O_AL + aoff + (uint32_t)t * (16 * KP * 2) + akb);
#pragma unroll
            for (int t = 0; t < 2; t++)
#pragma unroll
                for (int n = 0; n < 4; n++) mma16816(acc[t][n], al[t], b[n]);

#pragma unroll
            for (int p = 0; p < 2; p++)
                ldsm_x4t(b[2 * p][0], b[2 * p][1], b[2 * p + 1][0], b[2 * p + 1][1],
                         smb + O_BL + boff + bkb + (uint32_t)p * 32);
#pragma unroll
            for (int t = 0; t < 2; t++)
#pragma unroll
                for (int n = 0; n < 4; n++) mma16816(acc[t][n], ah[t], b[n]);
        }

        // ---- direct coalesced-sector writeout of xh fragments -------------------
#pragma unroll
        for (int t = 0; t < 2; t++)
#pragma unroll
            for (int n = 0; n < 4; n++) {
                int r = row0 + mrow + t * 16 + g;
                int c = ncol + n * 8 + tig * 2;
                if (r < N)
                    *(float2*)(g_xh + (size_t)r * 128 + c) = make_float2(acc[t][n][0], acc[t][n][1]);
                if (r + 8 < N)
                    *(float2*)(g_xh + (size_t)(r + 8) * 128 + c) = make_float2(acc[t][n][2], acc[t][n][3]);
            }

        // ---- partial scores ------------------------------------------------------
        float psi[4], psj[4];
#pragma unroll
        for (int t = 0; t < 2; t++)
#pragma unroll
            for (int h = 0; h < 2; h++) {
                float si = 0.f, sj = 0.f;
#pragma unroll
                for (int n = 0; n < 4; n++) {
                    int c = n * 8 + tig * 2;
                    float v0 = acc[t][n][h * 2 + 0];
                    float v1 = acc[t][n][h * 2 + 1];
                    si += v0 * attiq[c] + v1 * attiq[c + 1];
                    sj += v0 * attjq[c] + v1 * attjq[c + 1];
                }
                if (cg == 0) {
                    int grow = row0 + mrow + t * 16 + h * 8 + g;
                    if (grow < N) {
                        const float4* er = (const float4*)(emb + (size_t)grow * 64 + tig * 16);
#pragma unroll
                        for (int e4 = 0; e4 < 4; e4++) {
                            float4 e = er[e4];
                            si += e.x * aeiq[e4 * 4 + 0] + e.y * aeiq[e4 * 4 + 1]
                                + e.z * aeiq[e4 * 4 + 2] + e.w * aeiq[e4 * 4 + 3];
                            sj += e.x * aejq[e4 * 4 + 0] + e.y * aejq[e4 * 4 + 1]
                                + e.z * aejq[e4 * 4 + 2] + e.w * aejq[e4 * 4 + 3];
                        }
                    }
                }
                psi[t * 2 + h] = si;
                psj[t * 2 + h] = sj;
            }
#pragma unroll
        for (int r = 0; r < 4; r++) {
            psi[r] += __shfl_xor_sync(0xffffffffu, psi[r], 1);
            psi[r] += __shfl_xor_sync(0xffffffffu, psi[r], 2);
            psj[r] += __shfl_xor_sync(0xffffffffu, psj[r], 1);
            psj[r] += __shfl_xor_sync(0xffffffffu, psj[r], 2);
        }
        if (tig == 0) {
#pragma unroll
            for (int t = 0; t < 2; t++)
#pragma unroll
                for (int h = 0; h < 2; h++) {
                    int lrow = mrow + t * 16 + h * 8 + g;
                    psiA[(q * 2 + cg) * 64 + lrow] = psi[t * 2 + h];
                    psjA[(q * 2 + cg) * 64 + lrow] = psj[t * 2 + h];
                }
        }
        __syncthreads();

        if (tid < 64) {
            int grow = row0 + tid;
            if (grow < N) {
                float si0 = psiA[tid]       + psiA[64 + tid];
                float si1 = psiA[128 + tid] + psiA[192 + tid];
                float sj0 = psjA[tid]       + psjA[64 + tid];
                float sj1 = psjA[128 + tid] + psjA[192 + tid];
                *(float4*)(g_s + 4 * grow) = make_float4(si0, si1, sj0, sj1);
                g_wd[grow] = 0.0;
            }
        }
        __syncthreads();   // protect A tiles + psi arrays before next iteration
    }
}

// ---------------- Kernel 2: per-edge attention, 4 edges/thread ---------------
__device__ __forceinline__ float edge_alpha0(float2 si, float2 sj) {
    float a0 = si.x + sj.x;  a0 = fmaxf(a0, 0.2f * a0);
    float a1 = si.y + sj.y;  a1 = fmaxf(a1, 0.2f * a1);
    return __fdividef(1.0f, 1.0f + __expf(a1 - a0));   // = e0/(e0+e1)
}

__global__ void edge_kernel(const int* __restrict__ src, const int* __restrict__ dst,
                            int Eq)
{
    int i = blockIdx.x * blockDim.x + threadIdx.x;
    if (i >= Eq) return;
    int4 s4 = ((const int4*)src)[i];
    int4 d4 = ((const int4*)dst)[i];

    float2 si_a = *(const float2*)(g_s + 4 * s4.x);
    float2 sj_a = *(const float2*)(g_s + 4 * d4.x + 2);
    float2 si_b = *(const float2*)(g_s + 4 * s4.y);
    float2 sj_b = *(const float2*)(g_s + 4 * d4.y + 2);
    float2 si_c = *(const float2*)(g_s + 4 * s4.z);
    float2 sj_c = *(const float2*)(g_s + 4 * d4.z + 2);
    float2 si_d = *(const float2*)(g_s + 4 * s4.w);
    float2 sj_d = *(const float2*)(g_s + 4 * d4.w + 2);

    float aa = edge_alpha0(si_a, sj_a);
    float ab = edge_alpha0(si_b, sj_b);
    float ac = edge_alpha0(si_c, sj_c);
    float ad = edge_alpha0(si_d, sj_d);

    atomicAdd(g_wd + d4.x, (double)aa + 1048576.0);
    atomicAdd(g_wd + d4.y, (double)ab + 1048576.0);
    atomicAdd(g_wd + d4.z, (double)ac + 1048576.0);
    atomicAdd(g_wd + d4.w, (double)ad + 1048576.0);
}

// ---------------- Kernel 3: out = 0.5*(xh0*w0 + xh1*w1), 8 cols/thread -------
__global__ void out_kernel(float* __restrict__ out, int N)
{
    int i = blockIdx.x * blockDim.x + threadIdx.x;   // over N*8 items
    if (i >= N * 8) return;
    int n  = i >> 3;
    int d8 = (i & 7) << 3;

    float4 ss = *(const float4*)(g_s + 4 * n);
    float aself = edge_alpha0(make_float2(ss.x, ss.y), make_float2(ss.z, ss.w));

    double v   = g_wd[n];
    double deg = floor(v * 9.5367431640625e-07);       // v / 2^20
    float  w0  = (float)(v - deg * 1048576.0) + aself;
    float  w1  = ((float)deg + 1.0f) - w0;

    const float* xr = g_xh + (size_t)n * 128;
    float4 av0 = *(const float4*)(xr + d8);
    float4 av1 = *(const float4*)(xr + d8 + 4);
    float4 bv0 = *(const float4*)(xr + 64 + d8);
    float4 bv1 = *(const float4*)(xr + 64 + d8 + 4);

    float4 o0, o1;
    o0.x = 0.5f * (av0.x * w0 + bv0.x * w1);
    o0.y = 0.5f * (av0.y * w0 + bv0.y * w1);
    o0.z = 0.5f * (av0.z * w0 + bv0.z * w1);
    o0.w = 0.5f * (av0.w * w0 + bv0.w * w1);
    o1.x = 0.5f * (av1.x * w0 + bv1.x * w1);
    o1.y = 0.5f * (av1.y * w0 + bv1.y * w1);
    o1.z = 0.5f * (av1.z * w0 + bv1.z * w1);
    o1.w = 0.5f * (av1.w * w0 + bv1.w * w1);
    *(float4*)(out + (size_t)n * 64 + d8)     = o0;
    *(float4*)(out + (size_t)n * 64 + d8 + 4) = o1;
}

// ---------------- launcher ---------------------------------------------------
extern "C" void kernel_launch(void* const* d_in, const int* in_sizes, int n_in,
                              void* d_out, int out_size)
{
    const float* x    = (const float*)d_in[0];
    const float* emb  = (const float*)d_in[1];
    const float* W    = (const float*)d_in[2];
    const float* ai   = (const float*)d_in[3];
    const float* aj   = (const float*)d_in[4];
    const float* aei  = (const float*)d_in[5];
    const float* aej  = (const float*)d_in[6];
    const int*   esrc = (const int*)d_in[7];
    const int*   edst = (const int*)d_in[8];
    float* out = (float*)d_out;

    const int N = in_sizes[0] / 128;   // 50000
    const int E = in_sizes[7];         // 1600000 (divisible by 4)
    const int ntiles = (N + 63) / 64;  // 782
    int grid = 296;                    // 2 CTAs/SM x 148 SMs
    if (grid > ntiles) grid = ntiles;

    cudaFuncSetAttribute(fused_gemm_kernel,
                         cudaFuncAttributeMaxDynamicSharedMemorySize, SMEM_TOTAL);

    wsplit_kernel<<<16, 256>>>(W);
    fused_gemm_kernel<<<grid, 256, SMEM_TOTAL>>>(x, emb, ai, aj, aei, aej, N, ntiles);
    const int Eq = E / 4;
    edge_kernel<<<(Eq + 255) / 256, 256>>>(esrc, edst, Eq);
    out_kernel<<<(N * 8 + 255) / 256, 256>>>(out, N);
}

// round 11
// speedup vs baseline: 1.1380x; 1.0705x over previous
#include <cuda_runtime.h>
#include <cuda_fp16.h>
#include <cstdint>
#include <math.h>

// ---------------- scratch (device globals; no allocations allowed) ----------
#define NMAX 50000
__device__ float  g_xh[(size_t)NMAX * 128];  // [N, H*D] = [N,128]
__device__ float  g_s [NMAX * 4];            // (si0, si1, sj0, sj1) per node
__device__ double g_wd[NMAX];                // packed: deg*2^20 + sum(alpha0), excl self

// ---------------- PTX helpers (base sm_103 target) --------------------------
__device__ __forceinline__ uint32_t smem_u32(const void* p) {
    uint32_t a;
    asm("{ .reg .u64 t; cvta.to.shared.u64 t, %1; cvt.u32.u64 %0, t; }"
        : "=r"(a) : "l"(p));
    return a;
}
__device__ __forceinline__ void ldsm_x4(uint32_t& r0, uint32_t& r1,
                                        uint32_t& r2, uint32_t& r3, uint32_t addr) {
    asm volatile("ldmatrix.sync.aligned.m8n8.x4.shared.b16 {%0,%1,%2,%3}, [%4];"
                 : "=r"(r0), "=r"(r1), "=r"(r2), "=r"(r3) : "r"(addr));
}
__device__ __forceinline__ void ldsm_x4t(uint32_t& r0, uint32_t& r1,
                                         uint32_t& r2, uint32_t& r3, uint32_t addr) {
    asm volatile("ldmatrix.sync.aligned.m8n8.x4.trans.shared.b16 {%0,%1,%2,%3}, [%4];"
                 : "=r"(r0), "=r"(r1), "=r"(r2), "=r"(r3) : "r"(addr));
}
__device__ __forceinline__ void mma16816h(float* c, const uint32_t* a, const uint32_t* b) {
    asm volatile(
        "mma.sync.aligned.m16n8k16.row.col.f32.f16.f16.f32 "
        "{%0,%1,%2,%3}, {%4,%5,%6,%7}, {%8,%9}, {%0,%1,%2,%3};"
        : "+f"(c[0]), "+f"(c[1]), "+f"(c[2]), "+f"(c[3])
        : "r"(a[0]), "r"(a[1]), "r"(a[2]), "r"(a[3]), "r"(b[0]), "r"(b[1]));
}

__device__ __forceinline__ uint32_t packh2(__half a, __half b) {
    return (uint32_t)__half_as_ushort(a) | ((uint32_t)__half_as_ushort(b) << 16);
}
// fp16 hi/lo split of a float4
__device__ __forceinline__ void split4h(float4 v, uint2& hi, uint2& lo) {
    __half hx = __float2half_rn(v.x), hy = __float2half_rn(v.y);
    __half hz = __float2half_rn(v.z), hw = __float2half_rn(v.w);
    __half lx = __float2half_rn(v.x - __half2float(hx));
    __half ly = __float2half_rn(v.y - __half2float(hy));
    __half lz = __float2half_rn(v.z - __half2float(hz));
    __half lw = __float2half_rn(v.w - __half2float(hw));
    hi.x = packh2(hx, hy);  hi.y = packh2(hz, hw);
    lo.x = packh2(lx, ly);  lo.y = packh2(lz, lw);
}
// fp16 convert only (no residual) for B
__device__ __forceinline__ uint2 cvt4h(float4 v) {
    uint2 r;
    r.x = packh2(__float2half_rn(v.x), __float2half_rn(v.y));
    r.y = packh2(__float2half_rn(v.z), __float2half_rn(v.w));
    return r;
}

// ---------------- SMEM layout (bytes) ----------------------------------------
#define KP 136
#define O_ATT   0                       // 512 floats = 2048B
#define O_PSI   2048                    // 1024B
#define O_PSJ   3072                    // 1024B
#define O_AH    4096                    // A hi  [64 m][KP k] fp16 = 17408B
#define O_AL    (O_AH + 17408)          // A lo
#define O_BH    (O_AL + 17408)          // B hi  [128 k][KP n] fp16 = 34816B
#define SMEM_TOTAL (O_BH + 34816)       // 73728 -> 3 CTAs/SM

// ---------------- Kernel 1: persistent fused GEMM + scores -------------------
// 64-row x 128-col tile, 256 threads, fp16 2-term (AhBh + AlBh)
__global__ __launch_bounds__(256, 3)
void fused_gemm_kernel(const float* __restrict__ x,
                       const float* __restrict__ W,
                       const float* __restrict__ emb,
                       const float* __restrict__ ai,  const float* __restrict__ aj,
                       const float* __restrict__ aei, const float* __restrict__ aej,
                       int N, int ntiles)
{
    extern __shared__ char sm[];
    const uint32_t smb = smem_u32(sm);
    const int tid = threadIdx.x;
    const int wid = tid >> 5;
    const int lid = tid & 31;

    // ---- stage B ONCE: W fp32 -> fp16 (no split needed for 2-term scheme) ----
#pragma unroll
    for (int i = 0; i < 16; i++) {
        int idx = tid + i * 256;            // over 4096 float4s
        int k = idx >> 5, n = (idx & 31) * 4;
        float4 v = *(const float4*)(W + (size_t)k * 128 + n);
        uint32_t off = (uint32_t)(k * KP + n) * 2;
        *(uint2*)(sm + O_BH + off) = cvt4h(v);
    }
    // ---- stage attention vectors ---------------------------------------------
    {
        float* satt = (float*)(sm + O_ATT);
#pragma unroll
        for (int i = 0; i < 2; i++) {
            int t = tid + i * 256;
            float v;
            if      (t < 128) v = ai [t];
            else if (t < 256) v = aj [t - 128];
            else if (t < 384) v = aei[t - 256];
            else              v = aej[t - 384];
            satt[t] = v;
        }
    }

    // warp tile coords (constant across tiles)
    const int mrow = (wid & 1) * 32;
    const int ncol = (wid >> 1) * 32;
    const int q    = ncol >> 6;
    const int cg   = (ncol >> 5) & 1;
    const int g    = lid >> 2, tig = lid & 3;

    const int l15 = lid & 15;
    const int lh8 = (lid >> 4) * 8;
    const uint32_t aoff = (uint32_t)((mrow + l15) * KP + lh8) * 2;
    const int bkr = ((lid >> 3) & 1) * 8 + (lid & 7);
    const int bnc = (lid >> 4) * 8;
    const uint32_t boff = (uint32_t)(bkr * KP + ncol + bnc) * 2;

    const float* satt = (const float*)(sm + O_ATT);
    const float* attiq = satt + q * 64 + cg * 32;
    const float* attjq = satt + 128 + q * 64 + cg * 32;
    const float* aeiq  = satt + 256 + q * 64 + tig * 16;
    const float* aejq  = satt + 384 + q * 64 + tig * 16;
    float* psiA = (float*)(sm + O_PSI);
    float* psjA = (float*)(sm + O_PSJ);

    for (int tile = blockIdx.x; tile < ntiles; tile += gridDim.x) {
        const int row0 = tile * 64;

        // ---- stage A tile (fp16 hi/lo split) ------------------------------------
#pragma unroll
        for (int i = 0; i < 8; i++) {
            int idx = tid + i * 256;
            int r = idx >> 5, c = (idx & 31) * 4;
            float4 v = make_float4(0.f, 0.f, 0.f, 0.f);
            if (row0 + r < N) v = *(const float4*)(x + (size_t)(row0 + r) * 128 + c);
            uint2 hi, lo;
            split4h(v, hi, lo);
            uint32_t off = (uint32_t)(r * KP + c) * 2;
            *(uint2*)(sm + O_AH + off) = hi;
            *(uint2*)(sm + O_AL + off) = lo;
        }
        __syncthreads();

        // ---- MMA: 2 passes (AhBh, AlBh) x 8 K-steps ------------------------------
        float acc[2][4][4];
#pragma unroll
        for (int t = 0; t < 2; t++)
#pragma unroll
            for (int n = 0; n < 4; n++)
#pragma unroll
                for (int k = 0; k < 4; k++) acc[t][n][k] = 0.f;

#pragma unroll
        for (int ks = 0; ks < 8; ks++) {
            const uint32_t akb = (uint32_t)ks * 32;
            const uint32_t bkb = (uint32_t)ks * (16 * KP * 2);
            uint32_t ah[2][4], al[2][4], b[4][2];

#pragma unroll
            for (int t = 0; t < 2; t++)
                ldsm_x4(ah[t][0], ah[t][1], ah[t][2], ah[t][3],
                        smb + O_AH + aoff + (uint32_t)t * (16 * KP * 2) + akb);
#pragma unroll
            for (int p = 0; p < 2; p++)
                ldsm_x4t(b[2 * p][0], b[2 * p][1], b[2 * p + 1][0], b[2 * p + 1][1],
                         smb + O_BH + boff + bkb + (uint32_t)p * 32);
#pragma unroll
            for (int t = 0; t < 2; t++)
#pragma unroll
                for (int n = 0; n < 4; n++) mma16816h(acc[t][n], ah[t], b[n]);

#pragma unroll
            for (int t = 0; t < 2; t++)
                ldsm_x4(al[t][0], al[t][1], al[t][2], al[t][3],
                        smb + O_AL + aoff + (uint32_t)t * (16 * KP * 2) + akb);
#pragma unroll
            for (int t = 0; t < 2; t++)
#pragma unroll
                for (int n = 0; n < 4; n++) mma16816h(acc[t][n], al[t], b[n]);
        }

        // ---- direct coalesced-sector writeout of xh fragments -------------------
#pragma unroll
        for (int t = 0; t < 2; t++)
#pragma unroll
            for (int n = 0; n < 4; n++) {
                int r = row0 + mrow + t * 16 + g;
                int c = ncol + n * 8 + tig * 2;
                if (r < N)
                    *(float2*)(g_xh + (size_t)r * 128 + c) = make_float2(acc[t][n][0], acc[t][n][1]);
                if (r + 8 < N)
                    *(float2*)(g_xh + (size_t)(r + 8) * 128 + c) = make_float2(acc[t][n][2], acc[t][n][3]);
            }

        // ---- partial scores ------------------------------------------------------
        float psi[4], psj[4];
#pragma unroll
        for (int t = 0; t < 2; t++)
#pragma unroll
            for (int h = 0; h < 2; h++) {
                float si = 0.f, sj = 0.f;
#pragma unroll
                for (int n = 0; n < 4; n++) {
                    int c = n * 8 + tig * 2;
                    float v0 = acc[t][n][h * 2 + 0];
                    float v1 = acc[t][n][h * 2 + 1];
                    si += v0 * attiq[c] + v1 * attiq[c + 1];
                    sj += v0 * attjq[c] + v1 * attjq[c + 1];
                }
                if (cg == 0) {
                    int grow = row0 + mrow + t * 16 + h * 8 + g;
                    if (grow < N) {
                        const float4* er = (const float4*)(emb + (size_t)grow * 64 + tig * 16);
#pragma unroll
                        for (int e4 = 0; e4 < 4; e4++) {
                            float4 e = er[e4];
                            si += e.x * aeiq[e4 * 4 + 0] + e.y * aeiq[e4 * 4 + 1]
                                + e.z * aeiq[e4 * 4 + 2] + e.w * aeiq[e4 * 4 + 3];
                            sj += e.x * aejq[e4 * 4 + 0] + e.y * aejq[e4 * 4 + 1]
                                + e.z * aejq[e4 * 4 + 2] + e.w * aejq[e4 * 4 + 3];
                        }
                    }
                }
                psi[t * 2 + h] = si;
                psj[t * 2 + h] = sj;
            }
#pragma unroll
        for (int r = 0; r < 4; r++) {
            psi[r] += __shfl_xor_sync(0xffffffffu, psi[r], 1);
            psi[r] += __shfl_xor_sync(0xffffffffu, psi[r], 2);
            psj[r] += __shfl_xor_sync(0xffffffffu, psj[r], 1);
            psj[r] += __shfl_xor_sync(0xffffffffu, psj[r], 2);
        }
        if (tig == 0) {
#pragma unroll
            for (int t = 0; t < 2; t++)
#pragma unroll
                for (int h = 0; h < 2; h++) {
                    int lrow = mrow + t * 16 + h * 8 + g;
                    psiA[(q * 2 + cg) * 64 + lrow] = psi[t * 2 + h];
                    psjA[(q * 2 + cg) * 64 + lrow] = psj[t * 2 + h];
                }
        }
        __syncthreads();

        if (tid < 64) {
            int grow = row0 + tid;
            if (grow < N) {
                float si0 = psiA[tid]       + psiA[64 + tid];
                float si1 = psiA[128 + tid] + psiA[192 + tid];
                float sj0 = psjA[tid]       + psjA[64 + tid];
                float sj1 = psjA[128 + tid] + psjA[192 + tid];
                *(float4*)(g_s + 4 * grow) = make_float4(si0, si1, sj0, sj1);
                g_wd[grow] = 0.0;
            }
        }
        __syncthreads();   // protect A tiles + psi arrays before next iteration
    }
}

// ---------------- Kernel 2: per-edge attention, 4 edges/thread ---------------
__device__ __forceinline__ float edge_alpha0(float2 si, float2 sj) {
    float a0 = si.x + sj.x;  a0 = fmaxf(a0, 0.2f * a0);
    float a1 = si.y + sj.y;  a1 = fmaxf(a1, 0.2f * a1);
    return __fdividef(1.0f, 1.0f + __expf(a1 - a0));   // = e0/(e0+e1)
}

__global__ void edge_kernel(const int* __restrict__ src, const int* __restrict__ dst,
                            int Eq)
{
    int i = blockIdx.x * blockDim.x + threadIdx.x;
    if (i >= Eq) return;
    int4 s4 = ((const int4*)src)[i];
    int4 d4 = ((const int4*)dst)[i];

    float2 si_a = *(const float2*)(g_s + 4 * s4.x);
    float2 sj_a = *(const float2*)(g_s + 4 * d4.x + 2);
    float2 si_b = *(const float2*)(g_s + 4 * s4.y);
    float2 sj_b = *(const float2*)(g_s + 4 * d4.y + 2);
    float2 si_c = *(const float2*)(g_s + 4 * s4.z);
    float2 sj_c = *(const float2*)(g_s + 4 * d4.z + 2);
    float2 si_d = *(const float2*)(g_s + 4 * s4.w);
    float2 sj_d = *(const float2*)(g_s + 4 * d4.w + 2);

    float aa = edge_alpha0(si_a, sj_a);
    float ab = edge_alpha0(si_b, sj_b);
    float ac = edge_alpha0(si_c, sj_c);
    float ad = edge_alpha0(si_d, sj_d);

    atomicAdd(g_wd + d4.x, (double)aa + 1048576.0);
    atomicAdd(g_wd + d4.y, (double)ab + 1048576.0);
    atomicAdd(g_wd + d4.z, (double)ac + 1048576.0);
    atomicAdd(g_wd + d4.w, (double)ad + 1048576.0);
}

// ---------------- Kernel 3: out = 0.5*(xh0*w0 + xh1*w1), 8 cols/thread -------
__global__ void out_kernel(float* __restrict__ out, int N)
{
    int i = blockIdx.x * blockDim.x + threadIdx.x;   // over N*8 items
    if (i >= N * 8) return;
    int n  = i >> 3;
    int d8 = (i & 7) << 3;

    float4 ss = *(const float4*)(g_s + 4 * n);
    float aself = edge_alpha0(make_float2(ss.x, ss.y), make_float2(ss.z, ss.w));

    double v   = g_wd[n];
    double deg = floor(v * 9.5367431640625e-07);       // v / 2^20
    float  w0  = (float)(v - deg * 1048576.0) + aself;
    float  w1  = ((float)deg + 1.0f) - w0;

    const float* xr = g_xh + (size_t)n * 128;
    float4 av0 = *(const float4*)(xr + d8);
    float4 av1 = *(const float4*)(xr + d8 + 4);
    float4 bv0 = *(const float4*)(xr + 64 + d8);
    float4 bv1 = *(const float4*)(xr + 64 + d8 + 4);

    float4 o0, o1;
    o0.x = 0.5f * (av0.x * w0 + bv0.x * w1);
    o0.y = 0.5f * (av0.y * w0 + bv0.y * w1);
    o0.z = 0.5f * (av0.z * w0 + bv0.z * w1);
    o0.w = 0.5f * (av0.w * w0 + bv0.w * w1);
    o1.x = 0.5f * (av1.x * w0 + bv1.x * w1);
    o1.y = 0.5f * (av1.y * w0 + bv1.y * w1);
    o1.z = 0.5f * (av1.z * w0 + bv1.z * w1);
    o1.w = 0.5f * (av1.w * w0 + bv1.w * w1);
    *(float4*)(out + (size_t)n * 64 + d8)     = o0;
    *(float4*)(out + (size_t)n * 64 + d8 + 4) = o1;
}

// ---------------- launcher ---------------------------------------------------
extern "C" void kernel_launch(void* const* d_in, const int* in_sizes, int n_in,
                              void* d_out, int out_size)
{
    const float* x    = (const float*)d_in[0];
    const float* emb  = (const float*)d_in[1];
    const float* W    = (const float*)d_in[2];
    const float* ai   = (const float*)d_in[3];
    const float* aj   = (const float*)d_in[4];
    const float* aei  = (const float*)d_in[5];
    const float* aej  = (const float*)d_in[6];
    const int*   esrc = (const int*)d_in[7];
    const int*   edst = (const int*)d_in[8];
    float* out = (float*)d_out;

    const int N = in_sizes[0] / 128;   // 50000
    const int E = in_sizes[7];         // 1600000 (divisible by 4)
    const int ntiles = (N + 63) / 64;  // 782
    int grid = 444;                    // 3 CTAs/SM x 148 SMs
    if (grid > ntiles) grid = ntiles;

    cudaFuncSetAttribute(fused_gemm_kernel,
                         cudaFuncAttributeMaxDynamicSharedMemorySize, SMEM_TOTAL);

    fused_gemm_kernel<<<grid, 256, SMEM_TOTAL>>>(x, W, emb, ai, aj, aei, aej, N, ntiles);
    const int Eq = E / 4;
    edge_kernel<<<(Eq + 255) / 256, 256>>>(esrc, edst, Eq);
    out_kernel<<<(N * 8 + 255) / 256, 256>>>(out, N);
}

// round 12
// speedup vs baseline: 1.1537x; 1.0138x over previous
#include <cuda_runtime.h>
#include <cuda_fp16.h>
#include <cstdint>
#include <math.h>

// ---------------- scratch (device globals; no allocations allowed) ----------
#define NMAX 50000
__device__ float  g_xh[(size_t)NMAX * 128];  // [N, H*D] = [N,128]
__device__ float  g_s [NMAX * 4];            // (si0, si1, sj0, sj1) per node
__device__ double g_wd[NMAX];                // packed: deg*2^20 + sum(alpha0), excl self

// ---------------- PTX helpers (base sm_103 target) --------------------------
__device__ __forceinline__ uint32_t smem_u32(const void* p) {
    uint32_t a;
    asm("{ .reg .u64 t; cvta.to.shared.u64 t, %1; cvt.u32.u64 %0, t; }"
        : "=r"(a) : "l"(p));
    return a;
}
__device__ __forceinline__ void ldsm_x4(uint32_t& r0, uint32_t& r1,
                                        uint32_t& r2, uint32_t& r3, uint32_t addr) {
    asm volatile("ldmatrix.sync.aligned.m8n8.x4.shared.b16 {%0,%1,%2,%3}, [%4];"
                 : "=r"(r0), "=r"(r1), "=r"(r2), "=r"(r3) : "r"(addr));
}
__device__ __forceinline__ void ldsm_x4t(uint32_t& r0, uint32_t& r1,
                                         uint32_t& r2, uint32_t& r3, uint32_t addr) {
    asm volatile("ldmatrix.sync.aligned.m8n8.x4.trans.shared.b16 {%0,%1,%2,%3}, [%4];"
                 : "=r"(r0), "=r"(r1), "=r"(r2), "=r"(r3) : "r"(addr));
}
__device__ __forceinline__ void mma16816h(float* c, const uint32_t* a, const uint32_t* b) {
    asm volatile(
        "mma.sync.aligned.m16n8k16.row.col.f32.f16.f16.f32 "
        "{%0,%1,%2,%3}, {%4,%5,%6,%7}, {%8,%9}, {%0,%1,%2,%3};"
        : "+f"(c[0]), "+f"(c[1]), "+f"(c[2]), "+f"(c[3])
        : "r"(a[0]), "r"(a[1]), "r"(a[2]), "r"(a[3]), "r"(b[0]), "r"(b[1]));
}

__device__ __forceinline__ uint32_t packh2(__half a, __half b) {
    return (uint32_t)__half_as_ushort(a) | ((uint32_t)__half_as_ushort(b) << 16);
}
// fp16 convert of a float4 (plain, no residual)
__device__ __forceinline__ uint2 cvt4h(float4 v) {
    uint2 r;
    r.x = packh2(__float2half_rn(v.x), __float2half_rn(v.y));
    r.y = packh2(__float2half_rn(v.z), __float2half_rn(v.w));
    return r;
}

// ---------------- SMEM layout (bytes) ----------------------------------------
#define KP 136
#define O_ATT   0                       // 512 floats = 2048B
#define O_PSI   2048                    // 1024B
#define O_PSJ   3072                    // 1024B
#define O_AH    4096                    // A  [64 m][KP k] fp16 = 17408B
#define O_BH    (O_AH + 17408)          // B  [128 k][KP n] fp16 = 34816B
#define SMEM_TOTAL (O_BH + 34816)       // 56320 -> 4 CTAs/SM

// ---------------- Kernel 1: persistent fused GEMM + scores -------------------
// 64-row x 128-col tile, 256 threads, plain fp16 single-pass MMA
__global__ __launch_bounds__(256, 4)
void fused_gemm_kernel(const float* __restrict__ x,
                       const float* __restrict__ W,
                       const float* __restrict__ emb,
                       const float* __restrict__ ai,  const float* __restrict__ aj,
                       const float* __restrict__ aei, const float* __restrict__ aej,
                       int N, int ntiles)
{
    extern __shared__ char sm[];
    const uint32_t smb = smem_u32(sm);
    const int tid = threadIdx.x;
    const int wid = tid >> 5;
    const int lid = tid & 31;

    // ---- stage B ONCE: W fp32 -> fp16 -----------------------------------------
#pragma unroll
    for (int i = 0; i < 16; i++) {
        int idx = tid + i * 256;            // over 4096 float4s
        int k = idx >> 5, n = (idx & 31) * 4;
        float4 v = *(const float4*)(W + (size_t)k * 128 + n);
        uint32_t off = (uint32_t)(k * KP + n) * 2;
        *(uint2*)(sm + O_BH + off) = cvt4h(v);
    }
    // ---- stage attention vectors ---------------------------------------------
    {
        float* satt = (float*)(sm + O_ATT);
#pragma unroll
        for (int i = 0; i < 2; i++) {
            int t = tid + i * 256;
            float v;
            if      (t < 128) v = ai [t];
            else if (t < 256) v = aj [t - 128];
            else if (t < 384) v = aei[t - 256];
            else              v = aej[t - 384];
            satt[t] = v;
        }
    }

    // warp tile coords (constant across tiles)
    const int mrow = (wid & 1) * 32;
    const int ncol = (wid >> 1) * 32;
    const int q    = ncol >> 6;
    const int cg   = (ncol >> 5) & 1;
    const int g    = lid >> 2, tig = lid & 3;

    const int l15 = lid & 15;
    const int lh8 = (lid >> 4) * 8;
    const uint32_t aoff = (uint32_t)((mrow + l15) * KP + lh8) * 2;
    const int bkr = ((lid >> 3) & 1) * 8 + (lid & 7);
    const int bnc = (lid >> 4) * 8;
    const uint32_t boff = (uint32_t)(bkr * KP + ncol + bnc) * 2;

    const float* satt = (const float*)(sm + O_ATT);
    const float* attiq = satt + q * 64 + cg * 32;
    const float* attjq = satt + 128 + q * 64 + cg * 32;
    const float* aeiq  = satt + 256 + q * 64 + tig * 16;
    const float* aejq  = satt + 384 + q * 64 + tig * 16;
    float* psiA = (float*)(sm + O_PSI);
    float* psjA = (float*)(sm + O_PSJ);

    for (int tile = blockIdx.x; tile < ntiles; tile += gridDim.x) {
        const int row0 = tile * 64;

        // ---- stage A tile (fp16) -------------------------------------------------
#pragma unroll
        for (int i = 0; i < 8; i++) {
            int idx = tid + i * 256;
            int r = idx >> 5, c = (idx & 31) * 4;
            float4 v = make_float4(0.f, 0.f, 0.f, 0.f);
            if (row0 + r < N) v = *(const float4*)(x + (size_t)(row0 + r) * 128 + c);
            uint32_t off = (uint32_t)(r * KP + c) * 2;
            *(uint2*)(sm + O_AH + off) = cvt4h(v);
        }
        __syncthreads();

        // ---- MMA: single pass x 8 K-steps ----------------------------------------
        float acc[2][4][4];
#pragma unroll
        for (int t = 0; t < 2; t++)
#pragma unroll
            for (int n = 0; n < 4; n++)
#pragma unroll
                for (int k = 0; k < 4; k++) acc[t][n][k] = 0.f;

#pragma unroll
        for (int ks = 0; ks < 8; ks++) {
            const uint32_t akb = (uint32_t)ks * 32;
            const uint32_t bkb = (uint32_t)ks * (16 * KP * 2);
            uint32_t ah[2][4], b[4][2];

#pragma unroll
            for (int t = 0; t < 2; t++)
                ldsm_x4(ah[t][0], ah[t][1], ah[t][2], ah[t][3],
                        smb + O_AH + aoff + (uint32_t)t * (16 * KP * 2) + akb);
#pragma unroll
            for (int p = 0; p < 2; p++)
                ldsm_x4t(b[2 * p][0], b[2 * p][1], b[2 * p + 1][0], b[2 * p + 1][1],
                         smb + O_BH + boff + bkb + (uint32_t)p * 32);
#pragma unroll
            for (int t = 0; t < 2; t++)
#pragma unroll
                for (int n = 0; n < 4; n++) mma16816h(acc[t][n], ah[t], b[n]);
        }

        // ---- direct coalesced-sector writeout of xh fragments -------------------
#pragma unroll
        for (int t = 0; t < 2; t++)
#pragma unroll
            for (int n = 0; n < 4; n++) {
                int r = row0 + mrow + t * 16 + g;
                int c = ncol + n * 8 + tig * 2;
                if (r < N)
                    *(float2*)(g_xh + (size_t)r * 128 + c) = make_float2(acc[t][n][0], acc[t][n][1]);
                if (r + 8 < N)
                    *(float2*)(g_xh + (size_t)(r + 8) * 128 + c) = make_float2(acc[t][n][2], acc[t][n][3]);
            }

        // ---- partial scores ------------------------------------------------------
        float psi[4], psj[4];
#pragma unroll
        for (int t = 0; t < 2; t++)
#pragma unroll
            for (int h = 0; h < 2; h++) {
                float si = 0.f, sj = 0.f;
#pragma unroll
                for (int n = 0; n < 4; n++) {
                    int c = n * 8 + tig * 2;
                    float v0 = acc[t][n][h * 2 + 0];
                    float v1 = acc[t][n][h * 2 + 1];
                    si += v0 * attiq[c] + v1 * attiq[c + 1];
                    sj += v0 * attjq[c] + v1 * attjq[c + 1];
                }
                if (cg == 0) {
                    int grow = row0 + mrow + t * 16 + h * 8 + g;
                    if (grow < N) {
                        const float4* er = (const float4*)(emb + (size_t)grow * 64 + tig * 16);
#pragma unroll
                        for (int e4 = 0; e4 < 4; e4++) {
                            float4 e = er[e4];
                            si += e.x * aeiq[e4 * 4 + 0] + e.y * aeiq[e4 * 4 + 1]
                                + e.z * aeiq[e4 * 4 + 2] + e.w * aeiq[e4 * 4 + 3];
                            sj += e.x * aejq[e4 * 4 + 0] + e.y * aejq[e4 * 4 + 1]
                                + e.z * aejq[e4 * 4 + 2] + e.w * aejq[e4 * 4 + 3];
                        }
                    }
                }
                psi[t * 2 + h] = si;
                psj[t * 2 + h] = sj;
            }
#pragma unroll
        for (int r = 0; r < 4; r++) {
            psi[r] += __shfl_xor_sync(0xffffffffu, psi[r], 1);
            psi[r] += __shfl_xor_sync(0xffffffffu, psi[r], 2);
            psj[r] += __shfl_xor_sync(0xffffffffu, psj[r], 1);
            psj[r] += __shfl_xor_sync(0xffffffffu, psj[r], 2);
        }
        if (tig == 0) {
#pragma unroll
            for (int t = 0; t < 2; t++)
#pragma unroll
                for (int h = 0; h < 2; h++) {
                    int lrow = mrow + t * 16 + h * 8 + g;
                    psiA[(q * 2 + cg) * 64 + lrow] = psi[t * 2 + h];
                    psjA[(q * 2 + cg) * 64 + lrow] = psj[t * 2 + h];
                }
        }
        __syncthreads();

        if (tid < 64) {
            int grow = row0 + tid;
            if (grow < N) {
                float si0 = psiA[tid]       + psiA[64 + tid];
                float si1 = psiA[128 + tid] + psiA[192 + tid];
                float sj0 = psjA[tid]       + psjA[64 + tid];
                float sj1 = psjA[128 + tid] + psjA[192 + tid];
                *(float4*)(g_s + 4 * grow) = make_float4(si0, si1, sj0, sj1);
                g_wd[grow] = 0.0;
            }
        }
        __syncthreads();   // protect A tile + psi arrays before next iteration
    }
}

// ---------------- Kernel 2: per-edge attention, 4 edges/thread ---------------
__device__ __forceinline__ float edge_alpha0(float2 si, float2 sj) {
    float a0 = si.x + sj.x;  a0 = fmaxf(a0, 0.2f * a0);
    float a1 = si.y + sj.y;  a1 = fmaxf(a1, 0.2f * a1);
    return __fdividef(1.0f, 1.0f + __expf(a1 - a0));   // = e0/(e0+e1)
}

__global__ void edge_kernel(const int* __restrict__ src, const int* __restrict__ dst,
                            int Eq)
{
    int i = blockIdx.x * blockDim.x + threadIdx.x;
    if (i >= Eq) return;
    int4 s4 = ((const int4*)src)[i];
    int4 d4 = ((const int4*)dst)[i];

    float2 si_a = *(const float2*)(g_s + 4 * s4.x);
    float2 sj_a = *(const float2*)(g_s + 4 * d4.x + 2);
    float2 si_b = *(const float2*)(g_s + 4 * s4.y);
    float2 sj_b = *(const float2*)(g_s + 4 * d4.y + 2);
    float2 si_c = *(const float2*)(g_s + 4 * s4.z);
    float2 sj_c = *(const float2*)(g_s + 4 * d4.z + 2);
    float2 si_d = *(const float2*)(g_s + 4 * s4.w);
    float2 sj_d = *(const float2*)(g_s + 4 * d4.w + 2);

    float aa = edge_alpha0(si_a, sj_a);
    float ab = edge_alpha0(si_b, sj_b);
    float ac = edge_alpha0(si_c, sj_c);
    float ad = edge_alpha0(si_d, sj_d);

    atomicAdd(g_wd + d4.x, (double)aa + 1048576.0);
    atomicAdd(g_wd + d4.y, (double)ab + 1048576.0);
    atomicAdd(g_wd + d4.z, (double)ac + 1048576.0);
    atomicAdd(g_wd + d4.w, (double)ad + 1048576.0);
}

// ---------------- Kernel 3: out = 0.5*(xh0*w0 + xh1*w1), 8 cols/thread -------
__global__ void out_kernel(float* __restrict__ out, int N)
{
    int i = blockIdx.x * blockDim.x + threadIdx.x;   // over N*8 items
    if (i >= N * 8) return;
    int n  = i >> 3;
    int d8 = (i & 7) << 3;

    float4 ss = *(const float4*)(g_s + 4 * n);
    float aself = edge_alpha0(make_float2(ss.x, ss.y), make_float2(ss.z, ss.w));

    double v   = g_wd[n];
    double deg = floor(v * 9.5367431640625e-07);       // v / 2^20
    float  w0  = (float)(v - deg * 1048576.0) + aself;
    float  w1  = ((float)deg + 1.0f) - w0;

    const float* xr = g_xh + (size_t)n * 128;
    float4 av0 = *(const float4*)(xr + d8);
    float4 av1 = *(const float4*)(xr + d8 + 4);
    float4 bv0 = *(const float4*)(xr + 64 + d8);
    float4 bv1 = *(const float4*)(xr + 64 + d8 + 4);

    float4 o0, o1;
    o0.x = 0.5f * (av0.x * w0 + bv0.x * w1);
    o0.y = 0.5f * (av0.y * w0 + bv0.y * w1);
    o0.z = 0.5f * (av0.z * w0 + bv0.z * w1);
    o0.w = 0.5f * (av0.w * w0 + bv0.w * w1);
    o1.x = 0.5f * (av1.x * w0 + bv1.x * w1);
    o1.y = 0.5f * (av1.y * w0 + bv1.y * w1);
    o1.z = 0.5f * (av1.z * w0 + bv1.z * w1);
    o1.w = 0.5f * (av1.w * w0 + bv1.w * w1);
    *(float4*)(out + (size_t)n * 64 + d8)     = o0;
    *(float4*)(out + (size_t)n * 64 + d8 + 4) = o1;
}

// ---------------- launcher ---------------------------------------------------
extern "C" void kernel_launch(void* const* d_in, const int* in_sizes, int n_in,
                              void* d_out, int out_size)
{
    const float* x    = (const float*)d_in[0];
    const float* emb  = (const float*)d_in[1];
    const float* W    = (const float*)d_in[2];
    const float* ai   = (const float*)d_in[3];
    const float* aj   = (const float*)d_in[4];
    const float* aei  = (const float*)d_in[5];
    const float* aej  = (const float*)d_in[6];
    const int*   esrc = (const int*)d_in[7];
    const int*   edst = (const int*)d_in[8];
    float* out = (float*)d_out;

    const int N = in_sizes[0] / 128;   // 50000
    const int E = in_sizes[7];         // 1600000 (divisible by 4)
    const int ntiles = (N + 63) / 64;  // 782
    int grid = 592;                    // 4 CTAs/SM x 148 SMs
    if (grid > ntiles) grid = ntiles;

    cudaFuncSetAttribute(fused_gemm_kernel,
                         cudaFuncAttributeMaxDynamicSharedMemorySize, SMEM_TOTAL);

    fused_gemm_kernel<<<grid, 256, SMEM_TOTAL>>>(x, W, emb, ai, aj, aei, aej, N, ntiles);
    const int Eq = E / 4;
    edge_kernel<<<(Eq + 255) / 256, 256>>>(esrc, edst, Eq);
    out_kernel<<<(N * 8 + 255) / 256, 256>>>(out, N);
}

// round 14
// speedup vs baseline: 1.1901x; 1.0316x over previous
#include <cuda_runtime.h>
#include <cuda_fp16.h>
#include <cstdint>
#include <math.h>

// ---------------- scratch (device globals; no allocations allowed) ----------
#define NMAX 50000
__device__ __half g_xh[(size_t)NMAX * 128]; // [N, H*D] fp16
__device__ float  g_s [NMAX * 4];           // (si0, si1, sj0, sj1) per node
__device__ double g_wd[NMAX];               // packed: deg*2^20 + sum(alpha0), excl self
__device__ __half g_wh[128 * 128];          // W fp16, natural [k][n]

// ---------------- PTX helpers (base sm_103 target) --------------------------
__device__ __forceinline__ uint32_t smem_u32(const void* p) {
    uint32_t a;
    asm("{ .reg .u64 t; cvta.to.shared.u64 t, %1; cvt.u32.u64 %0, t; }"
        : "=r"(a) : "l"(p));
    return a;
}
__device__ __forceinline__ void ldsm_x4(uint32_t& r0, uint32_t& r1,
                                        uint32_t& r2, uint32_t& r3, uint32_t addr) {
    asm volatile("ldmatrix.sync.aligned.m8n8.x4.shared.b16 {%0,%1,%2,%3}, [%4];"
                 : "=r"(r0), "=r"(r1), "=r"(r2), "=r"(r3) : "r"(addr));
}
__device__ __forceinline__ void ldsm_x4t(uint32_t& r0, uint32_t& r1,
                                         uint32_t& r2, uint32_t& r3, uint32_t addr) {
    asm volatile("ldmatrix.sync.aligned.m8n8.x4.trans.shared.b16 {%0,%1,%2,%3}, [%4];"
                 : "=r"(r0), "=r"(r1), "=r"(r2), "=r"(r3) : "r"(addr));
}
__device__ __forceinline__ void mma16816h(float* c, const uint32_t* a, const uint32_t* b) {
    asm volatile(
        "mma.sync.aligned.m16n8k16.row.col.f32.f16.f16.f32 "
        "{%0,%1,%2,%3}, {%4,%5,%6,%7}, {%8,%9}, {%0,%1,%2,%3};"
        : "+f"(c[0]), "+f"(c[1]), "+f"(c[2]), "+f"(c[3])
        : "r"(a[0]), "r"(a[1]), "r"(a[2]), "r"(a[3]), "r"(b[0]), "r"(b[1]));
}

__device__ __forceinline__ uint32_t packh2(__half a, __half b) {
    return (uint32_t)__half_as_ushort(a) | ((uint32_t)__half_as_ushort(b) << 16);
}
__device__ __forceinline__ uint2 cvt4h(float4 v) {
    uint2 r;
    r.x = packh2(__float2half_rn(v.x), __float2half_rn(v.y));
    r.y = packh2(__float2half_rn(v.z), __float2half_rn(v.w));
    return r;
}

// ---------------- SMEM layout (bytes) ----------------------------------------
#define KP 136
#define O_ATT   0                       // 512 floats = 2048B
#define O_PSI   2048                    // 1024B
#define O_PSJ   3072                    // 1024B
#define O_AH    4096                    // A  [64 m][KP k] fp16 = 17408B
#define O_BH    (O_AH + 17408)          // B  [128 k][KP n] fp16 = 34816B
#define SMEM_TOTAL (O_BH + 34816)       // 56320 -> 4 CTAs/SM

// ---------------- Kernel 0: W fp32 -> fp16 (once) ----------------------------
__global__ void wconv_kernel(const float* __restrict__ W)
{
    int i = blockIdx.x * blockDim.x + threadIdx.x;   // over 4096 float4s
    if (i >= 128 * 128 / 4) return;
    ((uint2*)g_wh)[i] = cvt4h(((const float4*)W)[i]);
}

// ---------------- Kernel 1: persistent fused GEMM + scores -------------------
__global__ __launch_bounds__(256, 4)
void fused_gemm_kernel(const float* __restrict__ x,
                       const float* __restrict__ emb,
                       const float* __restrict__ ai,  const float* __restrict__ aj,
                       const float* __restrict__ aei, const float* __restrict__ aej,
                       int N, int ntiles)
{
    extern __shared__ char sm[];
    const uint32_t smb = smem_u32(sm);
    const int tid = threadIdx.x;
    const int wid = tid >> 5;
    const int lid = tid & 31;

    // ---- stage B ONCE: pure uint4 copy of precomputed fp16 W ------------------
#pragma unroll
    for (int i = 0; i < 8; i++) {
        int idx = tid + i * 256;            // over 2048 uint4s (8 fp16 each)
        int k = idx >> 4, n = (idx & 15) * 8;
        uint32_t off = (uint32_t)(k * KP + n) * 2;
        *(uint4*)(sm + O_BH + off) = ((const uint4*)g_wh)[idx];
    }
    // ---- stage attention vectors ---------------------------------------------
    {
        float* satt = (float*)(sm + O_ATT);
#pragma unroll
        for (int i = 0; i < 2; i++) {
            int t = tid + i * 256;
            float v;
            if      (t < 128) v = ai [t];
            else if (t < 256) v = aj [t - 128];
            else if (t < 384) v = aei[t - 256];
            else              v = aej[t - 384];
            satt[t] = v;
        }
    }

    // warp tile coords (constant across tiles)
    const int mrow = (wid & 1) * 32;
    const int ncol = (wid >> 1) * 32;
    const int q    = ncol >> 6;
    const int cg   = (ncol >> 5) & 1;
    const int g    = lid >> 2, tig = lid & 3;

    const int l15 = lid & 15;
    const int lh8 = (lid >> 4) * 8;
    const uint32_t aoff = (uint32_t)((mrow + l15) * KP + lh8) * 2;
    const int bkr = ((lid >> 3) & 1) * 8 + (lid & 7);
    const int bnc = (lid >> 4) * 8;
    const uint32_t boff = (uint32_t)(bkr * KP + ncol + bnc) * 2;

    const float* satt = (const float*)(sm + O_ATT);
    const float* attiq = satt + q * 64 + cg * 32;
    const float* attjq = satt + 128 + q * 64 + cg * 32;
    const float* aeiq  = satt + 256 + q * 64 + tig * 16;
    const float* aejq  = satt + 384 + q * 64 + tig * 16;
    float* psiA = (float*)(sm + O_PSI);
    float* psjA = (float*)(sm + O_PSJ);

    for (int tile = blockIdx.x; tile < ntiles; tile += gridDim.x) {
        const int row0 = tile * 64;

        // ---- stage A tile (fp16) -------------------------------------------------
#pragma unroll
        for (int i = 0; i < 8; i++) {
            int idx = tid + i * 256;
            int r = idx >> 5, c = (idx & 31) * 4;
            float4 v = make_float4(0.f, 0.f, 0.f, 0.f);
            if (row0 + r < N) v = *(const float4*)(x + (size_t)(row0 + r) * 128 + c);
            uint32_t off = (uint32_t)(r * KP + c) * 2;
            *(uint2*)(sm + O_AH + off) = cvt4h(v);
        }
        __syncthreads();

        // ---- MMA: single pass x 8 K-steps ----------------------------------------
        float acc[2][4][4];
#pragma unroll
        for (int t = 0; t < 2; t++)
#pragma unroll
            for (int n = 0; n < 4; n++)
#pragma unroll
                for (int k = 0; k < 4; k++) acc[t][n][k] = 0.f;

#pragma unroll
        for (int ks = 0; ks < 8; ks++) {
            const uint32_t akb = (uint32_t)ks * 32;
            const uint32_t bkb = (uint32_t)ks * (16 * KP * 2);
            uint32_t ah[2][4], b[4][2];

#pragma unroll
            for (int t = 0; t < 2; t++)
                ldsm_x4(ah[t][0], ah[t][1], ah[t][2], ah[t][3],
                        smb + O_AH + aoff + (uint32_t)t * (16 * KP * 2) + akb);
#pragma unroll
            for (int p = 0; p < 2; p++)
                ldsm_x4t(b[2 * p][0], b[2 * p][1], b[2 * p + 1][0], b[2 * p + 1][1],
                         smb + O_BH + boff + bkb + (uint32_t)p * 32);
#pragma unroll
            for (int t = 0; t < 2; t++)
#pragma unroll
                for (int n = 0; n < 4; n++) mma16816h(acc[t][n], ah[t], b[n]);
        }

        // ---- writeout of xh fragments as fp16 (__half2 per col-pair) -------------
#pragma unroll
        for (int t = 0; t < 2; t++)
#pragma unroll
            for (int n = 0; n < 4; n++) {
                int r = row0 + mrow + t * 16 + g;
                int c = ncol + n * 8 + tig * 2;
                if (r < N)
                    *(uint32_t*)(g_xh + (size_t)r * 128 + c) =
                        packh2(__float2half_rn(acc[t][n][0]), __float2half_rn(acc[t][n][1]));
                if (r + 8 < N)
                    *(uint32_t*)(g_xh + (size_t)(r + 8) * 128 + c) =
                        packh2(__float2half_rn(acc[t][n][2]), __float2half_rn(acc[t][n][3]));
            }

        // ---- partial scores ------------------------------------------------------
        float psi[4], psj[4];
#pragma unroll
        for (int t = 0; t < 2; t++)
#pragma unroll
            for (int h = 0; h < 2; h++) {
                float si = 0.f, sj = 0.f;
#pragma unroll
                for (int n = 0; n < 4; n++) {
                    int c = n * 8 + tig * 2;
                    float v0 = acc[t][n][h * 2 + 0];
                    float v1 = acc[t][n][h * 2 + 1];
                    si += v0 * attiq[c] + v1 * attiq[c + 1];
                    sj += v0 * attjq[c] + v1 * attjq[c + 1];
                }
                if (cg == 0) {
                    int grow = row0 + mrow + t * 16 + h * 8 + g;
                    if (grow < N) {
                        const float4* er = (const float4*)(emb + (size_t)grow * 64 + tig * 16);
#pragma unroll
                        for (int e4 = 0; e4 < 4; e4++) {
                            float4 e = er[e4];
                            si += e.x * aeiq[e4 * 4 + 0] + e.y * aeiq[e4 * 4 + 1]
                                + e.z * aeiq[e4 * 4 + 2] + e.w * aeiq[e4 * 4 + 3];
                            sj += e.x * aejq[e4 * 4 + 0] + e.y * aejq[e4 * 4 + 1]
                                + e.z * aejq[e4 * 4 + 2] + e.w * aejq[e4 * 4 + 3];
                        }
                    }
                }
                psi[t * 2 + h] = si;
                psj[t * 2 + h] = sj;
            }
#pragma unroll
        for (int r = 0; r < 4; r++) {
            psi[r] += __shfl_xor_sync(0xffffffffu, psi[r], 1);
            psi[r] += __shfl_xor_sync(0xffffffffu, psi[r], 2);
            psj[r] += __shfl_xor_sync(0xffffffffu, psj[r], 1);
            psj[r] += __shfl_xor_sync(0xffffffffu, psj[r], 2);
        }
        if (tig == 0) {
#pragma unroll
            for (int t = 0; t < 2; t++)
#pragma unroll
                for (int h = 0; h < 2; h++) {
                    int lrow = mrow + t * 16 + h * 8 + g;
                    psiA[(q * 2 + cg) * 64 + lrow] = psi[t * 2 + h];
                    psjA[(q * 2 + cg) * 64 + lrow] = psj[t * 2 + h];
                }
        }
        __syncthreads();

        if (tid < 64) {
            int grow = row0 + tid;
            if (grow < N) {
                float si0 = psiA[tid]       + psiA[64 + tid];
                float si1 = psiA[128 + tid] + psiA[192 + tid];
                float sj0 = psjA[tid]       + psjA[64 + tid];
                float sj1 = psjA[128 + tid] + psjA[192 + tid];
                *(float4*)(g_s + 4 * grow) = make_float4(si0, si1, sj0, sj1);
                g_wd[grow] = 0.0;
            }
        }
        __syncthreads();   // protect A tile + psi arrays before next iteration
    }
}

// ---------------- Kernel 2: per-edge attention, 4 edges/thread ---------------
__device__ __forceinline__ float edge_alpha0(float2 si, float2 sj) {
    float a0 = si.x + sj.x;  a0 = fmaxf(a0, 0.2f * a0);
    float a1 = si.y + sj.y;  a1 = fmaxf(a1, 0.2f * a1);
    return __fdividef(1.0f, 1.0f + __expf(a1 - a0));   // = e0/(e0+e1)
}

__global__ void edge_kernel(const int* __restrict__ src, const int* __restrict__ dst,
                            int Eq)
{
    int i = blockIdx.x * blockDim.x + threadIdx.x;
    if (i >= Eq) return;
    int4 s4 = ((const int4*)src)[i];
    int4 d4 = ((const int4*)dst)[i];

    float2 si_a = *(const float2*)(g_s + 4 * s4.x);
    float2 sj_a = *(const float2*)(g_s + 4 * d4.x + 2);
    float2 si_b = *(const float2*)(g_s + 4 * s4.y);
    float2 sj_b = *(const float2*)(g_s + 4 * d4.y + 2);
    float2 si_c = *(const float2*)(g_s + 4 * s4.z);
    float2 sj_c = *(const float2*)(g_s + 4 * d4.z + 2);
    float2 si_d = *(const float2*)(g_s + 4 * s4.w);
    float2 sj_d = *(const float2*)(g_s + 4 * d4.w + 2);

    float aa = edge_alpha0(si_a, sj_a);
    float ab = edge_alpha0(si_b, sj_b);
    float ac = edge_alpha0(si_c, sj_c);
    float ad = edge_alpha0(si_d, sj_d);

    atomicAdd(g_wd + d4.x, (double)aa + 1048576.0);
    atomicAdd(g_wd + d4.y, (double)ab + 1048576.0);
    atomicAdd(g_wd + d4.z, (double)ac + 1048576.0);
    atomicAdd(g_wd + d4.w, (double)ad + 1048576.0);
}

// ---------------- Kernel 3: out = 0.5*(xh0*w0 + xh1*w1), 8 cols/thread -------
__global__ void out_kernel(float* __restrict__ out, int N)
{
    int i = blockIdx.x * blockDim.x + threadIdx.x;   // over N*8 items
    if (i >= N * 8) return;
    int n  = i >> 3;
    int d8 = (i & 7) << 3;

    float4 ss = *(const float4*)(g_s + 4 * n);
    float aself = edge_alpha0(make_float2(ss.x, ss.y), make_float2(ss.z, ss.w));

    double v   = g_wd[n];
    double deg = floor(v * 9.5367431640625e-07);       // v / 2^20
    float  w0  = (float)(v - deg * 1048576.0) + aself;
    float  w1  = ((float)deg + 1.0f) - w0;

    const __half* xr = g_xh + (size_t)n * 128;
    uint4 ap = *(const uint4*)(xr + d8);        // 8 fp16: head0 cols
    uint4 bp = *(const uint4*)(xr + 64 + d8);   // 8 fp16: head1 cols

    const uint32_t* au = (const uint32_t*)&ap;
    const uint32_t* bu = (const uint32_t*)&bp;
    float o[8];
#pragma unroll
    for (int k = 0; k < 4; k++) {
        float2 a2 = __half22float2(*(const __half2*)&au[k]);
        float2 b2 = __half22float2(*(const __half2*)&bu[k]);
        o[k * 2 + 0] = 0.5f * (a2.x * w0 + b2.x * w1);
        o[k * 2 + 1] = 0.5f * (a2.y * w0 + b2.y * w1);
    }
    *(float4*)(out + (size_t)n * 64 + d8)     = make_float4(o[0], o[1], o[2], o[3]);
    *(float4*)(out + (size_t)n * 64 + d8 + 4) = make_float4(o[4], o[5], o[6], o[7]);
}

// ---------------- launcher ---------------------------------------------------
extern "C" void kernel_launch(void* const* d_in, const int* in_sizes, int n_in,
                              void* d_out, int out_size)
{
    const float* x    = (const float*)d_in[0];
    const float* emb  = (const float*)d_in[1];
    const float* W    = (const float*)d_in[2];
    const float* ai   = (const float*)d_in[3];
    const float* aj   = (const float*)d_in[4];
    const float* aei  = (const float*)d_in[5];
    const float* aej  = (const float*)d_in[6];
    const int*   esrc = (const int*)d_in[7];
    const int*   edst = (const int*)d_in[8];
    float* out = (float*)d_out;

    const int N = in_sizes[0] / 128;   // 50000
    const int E = in_sizes[7];         // 1600000 (divisible by 4)
    const int ntiles = (N + 63) / 64;  // 782
    int grid = 592;                    // 4 CTAs/SM x 148 SMs
    if (grid > ntiles) grid = ntiles;

    cudaFuncSetAttribute(fused_gemm_kernel,
                         cudaFuncAttributeMaxDynamicSharedMemorySize, SMEM_TOTAL);

    wconv_kernel<<<16, 256>>>(W);
    fused_gemm_kernel<<<grid, 256, SMEM_TOTAL>>>(x, emb, ai, aj, aei, aej, N, ntiles);
    const int Eq = E / 4;
    edge_kernel<<<(Eq + 255) / 256, 256>>>(esrc, edst, Eq);
    out_kernel<<<(N * 8 + 255) / 256, 256>>>(out, N);
}